// round 13
// baseline (speedup 1.0000x reference)
#include <cuda_runtime.h>
#include <cuda_fp16.h>
#include <mma.h>

using namespace nvcuda;

#define N_NODES 100000
#define N_EDGES 1600000
#define IN_DIM  128
#define HID     64
#define SCAN_CHUNK 1024
#define NSCAN_BLOCKS ((N_NODES + SCAN_CHUNK - 1) / SCAN_CHUNK)   // 98
#define NBLK_TC ((N_NODES + 63) / 64)                             // 1563

// ---- scratch (static device globals; no runtime allocation) ----
__device__ __align__(16) __half g_y [(size_t)N_NODES * HID];  // per-layer GEMM output (gathered)
__device__ __align__(16) __half g_h [(size_t)N_NODES * HID];  // layer-1 activation
__device__ __align__(16) __half g_h2[(size_t)N_NODES * HID];  // layer-2 embedding
__device__ __align__(16) __half g_Hs[(size_t)N_NODES * HID];  // gathered by score
__device__ __align__(16) __half g_Hd[(size_t)N_NODES * HID];  // gathered by score
__device__ float g_norm_out[N_NODES];
__device__ float g_norm_in[N_NODES];
__device__ int   g_deg_out[N_NODES];   // zero at entry/exit of every run
__device__ int   g_deg_in[N_NODES];    // zero at entry/exit of every run
__device__ int   g_row_start[N_NODES];
__device__ int   g_cursor[N_NODES];    // after csr_fill: row END
__device__ int   g_bsum[NSCAN_BLOCKS];
__device__ int   g_csr[N_EDGES];

union HPack { uint2 u; __half2 h[2]; };
union HPack4 { uint4 u; __half2 h[4]; };

__device__ __forceinline__ void f4_to_h4(__half* d, float4 f) {
    HPack pk;
    pk.h[0] = __floats2half2_rn(f.x, f.y);
    pk.h[1] = __floats2half2_rn(f.z, f.w);
    *(uint2*)d = pk.u;
}

// ---- 1: degree histogram (4 edges/thread, int4 loads) ----
__global__ void k_deg(const int* __restrict__ src, const int* __restrict__ dst) {
    int i = blockIdx.x * blockDim.x + threadIdx.x;
    if (i < N_EDGES / 4) {
        int4 s4 = ((const int4*)src)[i];
        int4 d4 = ((const int4*)dst)[i];
        atomicAdd(&g_deg_out[s4.x], 1); atomicAdd(&g_deg_out[s4.y], 1);
        atomicAdd(&g_deg_out[s4.z], 1); atomicAdd(&g_deg_out[s4.w], 1);
        atomicAdd(&g_deg_in[d4.x], 1);  atomicAdd(&g_deg_in[d4.y], 1);
        atomicAdd(&g_deg_in[d4.z], 1);  atomicAdd(&g_deg_in[d4.w], 1);
    }
}

// ---- 2a: per-1024-chunk scan of deg_in ----
__global__ __launch_bounds__(256) void k_scan_local() {
    __shared__ int sh[256];
    int t = threadIdx.x;
    int base = blockIdx.x * SCAN_CHUNK + t * 4;
    int d0 = (base + 0 < N_NODES) ? g_deg_in[base + 0] : 0;
    int d1 = (base + 1 < N_NODES) ? g_deg_in[base + 1] : 0;
    int d2 = (base + 2 < N_NODES) ? g_deg_in[base + 2] : 0;
    int d3 = (base + 3 < N_NODES) ? g_deg_in[base + 3] : 0;
    int s = d0 + d1 + d2 + d3;
    sh[t] = s;
    __syncthreads();
    for (int off = 1; off < 256; off <<= 1) {
        int tmp = (t >= off) ? sh[t - off] : 0;
        __syncthreads();
        sh[t] += tmp;
        __syncthreads();
    }
    int excl = sh[t] - s;
    int r0 = excl, r1 = r0 + d0, r2 = r1 + d1, r3 = r2 + d2;
    if (base + 0 < N_NODES) g_row_start[base + 0] = r0;
    if (base + 1 < N_NODES) g_row_start[base + 1] = r1;
    if (base + 2 < N_NODES) g_row_start[base + 2] = r2;
    if (base + 3 < N_NODES) g_row_start[base + 3] = r3;
    if (t == 255) g_bsum[blockIdx.x] = sh[255];
}

// ---- 2b: finalize offsets + cursors + norms; zero counters for next run ----
__global__ __launch_bounds__(256) void k_scan_add() {
    __shared__ int orig[128], scn[128];
    int t = threadIdx.x;
    if (t < 128) {
        int v = (t < NSCAN_BLOCKS) ? g_bsum[t] : 0;
        orig[t] = v; scn[t] = v;
    }
    __syncthreads();
    for (int off = 1; off < 128; off <<= 1) {
        int tmp = (t < 128 && t >= off) ? scn[t - off] : 0;
        __syncthreads();
        if (t < 128) scn[t] += tmp;
        __syncthreads();
    }
    int i = blockIdx.x * blockDim.x + t;
    if (i < N_NODES) {
        int c = i >> 10;
        int dout = g_deg_out[i], din = g_deg_in[i];
        int r = g_row_start[i] + (scn[c] - orig[c]);
        g_row_start[i] = r;
        g_cursor[i] = r;
        g_norm_out[i] = rsqrtf(fmaxf((float)dout, 1.f));
        g_norm_in[i]  = rsqrtf(fmaxf((float)din,  1.f));
        g_deg_out[i] = 0;
        g_deg_in[i]  = 0;
    }
}

// ---- 2c: fill CSR (4 edges/thread; cursor[v] ends at row END) ----
__global__ void k_csr_fill(const int* __restrict__ src, const int* __restrict__ dst) {
    int i = blockIdx.x * blockDim.x + threadIdx.x;
    if (i < N_EDGES / 4) {
        int4 s4 = ((const int4*)src)[i];
        int4 d4 = ((const int4*)dst)[i];
        int p0 = atomicAdd(&g_cursor[d4.x], 1); g_csr[p0] = s4.x;
        int p1 = atomicAdd(&g_cursor[d4.y], 1); g_csr[p1] = s4.y;
        int p2 = atomicAdd(&g_cursor[d4.z], 1); g_csr[p2] = s4.z;
        int p3 = atomicAdd(&g_cursor[d4.w], 1); g_csr[p3] = s4.w;
    }
}

// ---- 3: y = (x @ W1) * norm_out -> fp16 (launched AFTER scan_add; norms ready) ----
__global__ __launch_bounds__(256) void k_gemm1_tc(const float* __restrict__ x,
                                                  const float* __restrict__ W1) {
    __shared__ __align__(256) char sbuf[35840];
    half*  As = (half*)sbuf;                // [64][136]
    half*  Bs = (half*)(sbuf + 17408);      // [128][72]
    float* Cs = (float*)sbuf;               // [64][72] (alias)
    const int tid = threadIdx.x;
    const int wid = tid >> 5;
    const int v0 = blockIdx.x * 64;

    for (int i = tid; i < 128 * 16; i += 256) {
        int r = i >> 4, c4 = i & 15;
        f4_to_h4(Bs + r * 72 + c4 * 4, ((const float4*)W1)[i]);
    }
    for (int i = tid; i < 64 * 32; i += 256) {
        int r = i >> 5, c4 = i & 31;
        int v = v0 + r;
        float4 xv = (v < N_NODES) ? ((const float4*)(x + (size_t)v * IN_DIM))[c4]
                                  : make_float4(0.f, 0.f, 0.f, 0.f);
        f4_to_h4(As + r * 136 + c4 * 4, xv);
    }
    __syncthreads();

    const int wm = wid >> 1, wn = wid & 1;
    wmma::fragment<wmma::accumulator, 16, 16, 16, float> c0, c1;
    wmma::fill_fragment(c0, 0.f);
    wmma::fill_fragment(c1, 0.f);
    #pragma unroll
    for (int k0 = 0; k0 < 128; k0 += 16) {
        wmma::fragment<wmma::matrix_a, 16, 16, 16, half, wmma::row_major> a;
        wmma::fragment<wmma::matrix_b, 16, 16, 16, half, wmma::row_major> b0, b1;
        wmma::load_matrix_sync(a, As + wm * 16 * 136 + k0, 136);
        wmma::load_matrix_sync(b0, Bs + k0 * 72 + wn * 32, 72);
        wmma::load_matrix_sync(b1, Bs + k0 * 72 + wn * 32 + 16, 72);
        wmma::mma_sync(c0, a, b0, c0);
        wmma::mma_sync(c1, a, b1, c1);
    }
    __syncthreads();
    wmma::store_matrix_sync(Cs + wm * 16 * 72 + wn * 32,      c0, 72, wmma::mem_row_major);
    wmma::store_matrix_sync(Cs + wm * 16 * 72 + wn * 32 + 16, c1, 72, wmma::mem_row_major);
    __syncthreads();
    for (int i = tid; i < 64 * 16; i += 256) {
        int r = i >> 4, cq = i & 15;
        int v = v0 + r;
        if (v < N_NODES) {
            float n = g_norm_out[v];
            float4 f = ((const float4*)(Cs + r * 72))[cq];
            f.x *= n; f.y *= n; f.z *= n; f.w *= n;
            f4_to_h4(g_y + (size_t)v * HID + cq * 4, f);
        }
    }
}

// ---- 4/7: CSR gather (dual-edge half-warp, plain sum; y is pre-scaled).
// phase 0: +b1, relu -> g_h ; phase 1: +b2 -> g_h2
__global__ __launch_bounds__(256) void k_gather(const float* __restrict__ bias, int phase) {
    int v    = (blockIdx.x * blockDim.x + threadIdx.x) >> 5;
    int lane = threadIdx.x & 31;
    if (v >= N_NODES) return;
    const int hw = lane >> 4;
    const int hl = lane & 15;
    __half* out = phase ? g_h2 : g_h;
    int beg = g_row_start[v];
    int end = g_cursor[v];
    const uint2* Y2 = (const uint2*)g_y;
    float a0 = 0.f, a1 = 0.f, a2 = 0.f, a3 = 0.f;
    int j = beg;
    for (; j + 15 < end; j += 16) {
        int base = j + hw * 8;
        #pragma unroll
        for (int k = 0; k < 8; k++) {
            int s = g_csr[base + k];
            HPack pk; pk.u = Y2[(size_t)s * 16 + hl];
            float2 f0 = __half22float2(pk.h[0]);
            float2 f1 = __half22float2(pk.h[1]);
            a0 += f0.x; a1 += f0.y; a2 += f1.x; a3 += f1.y;
        }
    }
    for (; j < end; j += 2) {
        int idx = j + hw;
        if (idx < end) {
            int s = g_csr[idx];
            HPack pk; pk.u = Y2[(size_t)s * 16 + hl];
            float2 f0 = __half22float2(pk.h[0]);
            float2 f1 = __half22float2(pk.h[1]);
            a0 += f0.x; a1 += f0.y; a2 += f1.x; a3 += f1.y;
        }
    }
    a0 += __shfl_xor_sync(0xffffffffu, a0, 16);
    a1 += __shfl_xor_sync(0xffffffffu, a1, 16);
    a2 += __shfl_xor_sync(0xffffffffu, a2, 16);
    a3 += __shfl_xor_sync(0xffffffffu, a3, 16);
    if (hw == 0) {
        float ni = g_norm_in[v];
        float4 bv = ((const float4*)bias)[hl];
        float r0 = a0 * ni + bv.x;
        float r1 = a1 * ni + bv.y;
        float r2 = a2 * ni + bv.z;
        float r3 = a3 * ni + bv.w;
        if (phase == 0) {
            r0 = fmaxf(r0, 0.f); r1 = fmaxf(r1, 0.f);
            r2 = fmaxf(r2, 0.f); r3 = fmaxf(r3, 0.f);
        }
        HPack pk;
        pk.h[0] = __floats2half2_rn(r0, r1);
        pk.h[1] = __floats2half2_rn(r2, r3);
        ((uint2*)(out + (size_t)v * HID))[hl] = pk.u;
    }
}

// ---- 6: y = (h @ W2) * norm_out -> fp16. PDL: W2 preamble, then grid-dep sync ----
__global__ __launch_bounds__(256) void k_gemm2_tc(const float* __restrict__ W2) {
    __shared__ __align__(256) char sbuf[18432];
    half*  As = (half*)sbuf;                // [64][72]
    half*  Bs = (half*)(sbuf + 9216);       // [64][72]
    float* Cs = (float*)sbuf;               // [64][72] (alias)
    const int tid = threadIdx.x;
    const int wid = tid >> 5;
    const int v0 = blockIdx.x * 64;

    for (int i = tid; i < 64 * 16; i += 256) {            // W2 (input): dep-free preamble
        int r = i >> 4, c4 = i & 15;
        f4_to_h4(Bs + r * 72 + c4 * 4, ((const float4*)W2)[i]);
    }
    cudaGridDependencySynchronize();                      // wait for gather0's g_h
    for (int i = tid; i < 64 * 8; i += 256) {
        int r = i >> 3, c8 = i & 7;
        int v = v0 + r;
        uint4 hv = (v < N_NODES) ? ((const uint4*)(g_h + (size_t)v * HID))[c8]
                                 : make_uint4(0u, 0u, 0u, 0u);
        *(uint4*)(As + r * 72 + c8 * 8) = hv;
    }
    __syncthreads();

    const int wm = wid >> 1, wn = wid & 1;
    wmma::fragment<wmma::accumulator, 16, 16, 16, float> c0, c1;
    wmma::fill_fragment(c0, 0.f);
    wmma::fill_fragment(c1, 0.f);
    #pragma unroll
    for (int k0 = 0; k0 < 64; k0 += 16) {
        wmma::fragment<wmma::matrix_a, 16, 16, 16, half, wmma::row_major> a;
        wmma::fragment<wmma::matrix_b, 16, 16, 16, half, wmma::row_major> b0, b1;
        wmma::load_matrix_sync(a, As + wm * 16 * 72 + k0, 72);
        wmma::load_matrix_sync(b0, Bs + k0 * 72 + wn * 32, 72);
        wmma::load_matrix_sync(b1, Bs + k0 * 72 + wn * 32 + 16, 72);
        wmma::mma_sync(c0, a, b0, c0);
        wmma::mma_sync(c1, a, b1, c1);
    }
    __syncthreads();
    wmma::store_matrix_sync(Cs + wm * 16 * 72 + wn * 32,      c0, 72, wmma::mem_row_major);
    wmma::store_matrix_sync(Cs + wm * 16 * 72 + wn * 32 + 16, c1, 72, wmma::mem_row_major);
    __syncthreads();
    for (int i = tid; i < 64 * 16; i += 256) {
        int r = i >> 4, cq = i & 15;
        int v = v0 + r;
        if (v < N_NODES) {
            float n = g_norm_out[v];
            float4 f = ((const float4*)(Cs + r * 72))[cq];
            f.x *= n; f.y *= n; f.z *= n; f.w *= n;
            f4_to_h4(g_y + (size_t)v * HID + cq * 4, f);
        }
    }
}

// ---- 8: [Hs|Hd] = h2 @ [W3top|W3bot] (+b3 on Hs) -> fp16. PDL preamble on W3 ----
__global__ __launch_bounds__(256) void k_post_tc(const float* __restrict__ W3,
                                                 const float* __restrict__ b3v) {
    __shared__ __align__(256) char sbuf[34816];
    half*  As = (half*)sbuf;                // [64][72]
    half*  Bs = (half*)(sbuf + 9216);       // [64][136]
    float* Cs = (float*)sbuf;               // [64][136] (alias)
    const int tid = threadIdx.x;
    const int wid = tid >> 5;
    const int v0 = blockIdx.x * 64;

    // B[k][n] = n<64 ? W3[k][n] : W3[64+k][n-64]  (input: dep-free preamble)
    for (int i = tid; i < 64 * 32; i += 256) {
        int k = i >> 5, c4 = i & 31;
        int n = c4 * 4;
        const float4* srcp = (n < 64)
            ? (const float4*)(W3 + (size_t)k * 64 + n)
            : (const float4*)(W3 + (size_t)(64 + k) * 64 + (n - 64));
        f4_to_h4(Bs + k * 136 + n, *srcp);
    }
    cudaGridDependencySynchronize();                      // wait for gather1's g_h2
    for (int i = tid; i < 64 * 8; i += 256) {
        int r = i >> 3, c8 = i & 7;
        int v = v0 + r;
        uint4 hv = (v < N_NODES) ? ((const uint4*)(g_h2 + (size_t)v * HID))[c8]
                                 : make_uint4(0u, 0u, 0u, 0u);
        *(uint4*)(As + r * 72 + c8 * 8) = hv;
    }
    __syncthreads();

    const int wm = wid >> 2, wn = wid & 3;
    wmma::fragment<wmma::accumulator, 16, 16, 16, float> c00, c01, c10, c11;
    wmma::fill_fragment(c00, 0.f); wmma::fill_fragment(c01, 0.f);
    wmma::fill_fragment(c10, 0.f); wmma::fill_fragment(c11, 0.f);
    #pragma unroll
    for (int k0 = 0; k0 < 64; k0 += 16) {
        wmma::fragment<wmma::matrix_a, 16, 16, 16, half, wmma::row_major> a0, a1;
        wmma::fragment<wmma::matrix_b, 16, 16, 16, half, wmma::row_major> b0, b1;
        wmma::load_matrix_sync(a0, As + (wm * 32)      * 72 + k0, 72);
        wmma::load_matrix_sync(a1, As + (wm * 32 + 16) * 72 + k0, 72);
        wmma::load_matrix_sync(b0, Bs + k0 * 136 + wn * 32,      136);
        wmma::load_matrix_sync(b1, Bs + k0 * 136 + wn * 32 + 16, 136);
        wmma::mma_sync(c00, a0, b0, c00);
        wmma::mma_sync(c01, a0, b1, c01);
        wmma::mma_sync(c10, a1, b0, c10);
        wmma::mma_sync(c11, a1, b1, c11);
    }
    __syncthreads();
    wmma::store_matrix_sync(Cs + (wm * 32)      * 136 + wn * 32,      c00, 136, wmma::mem_row_major);
    wmma::store_matrix_sync(Cs + (wm * 32)      * 136 + wn * 32 + 16, c01, 136, wmma::mem_row_major);
    wmma::store_matrix_sync(Cs + (wm * 32 + 16) * 136 + wn * 32,      c10, 136, wmma::mem_row_major);
    wmma::store_matrix_sync(Cs + (wm * 32 + 16) * 136 + wn * 32 + 16, c11, 136, wmma::mem_row_major);
    __syncthreads();
    for (int i = tid; i < 64 * 32; i += 256) {
        int r = i >> 5, c4 = i & 31;
        int col = c4 * 4;
        int v = v0 + r;
        if (v < N_NODES) {
            float4 f = *(const float4*)(Cs + r * 136 + col);
            if (col < 64) {
                float4 b = *(const float4*)(b3v + col);
                f.x += b.x; f.y += b.y; f.z += b.z; f.w += b.w;
                f4_to_h4(g_Hs + (size_t)v * HID + col, f);
            } else {
                f4_to_h4(g_Hd + (size_t)v * HID + (col - 64), f);
            }
        }
    }
}

// ---- 9: per-edge score. PDL preamble: edge indices + W4 (inputs, dep-free) ----
__global__ __launch_bounds__(256) void k_score(const int* __restrict__ sn,
                                               const int* __restrict__ dn,
                                               const float* __restrict__ W4,
                                               const float* __restrict__ b4,
                                               float* __restrict__ out) {
    long long t = (long long)blockIdx.x * blockDim.x + threadIdx.x;
    int e = (int)(t >> 3);
    int l = (int)t & 7;
    if (e >= N_EDGES) {
        cudaGridDependencySynchronize();
        return;
    }
    int s = __ldg(&sn[e]);
    int d = __ldg(&dn[e]);
    float4 w0 = __ldg((const float4*)W4 + 2 * l);
    float4 w1 = __ldg((const float4*)W4 + 2 * l + 1);
    float bias = __ldg(&b4[0]);
    cudaGridDependencySynchronize();                      // wait for Hs/Hd
    HPack4 a, b;
    a.u = ((const uint4*)(g_Hs + (size_t)s * HID))[l];
    b.u = ((const uint4*)(g_Hd + (size_t)d * HID))[l];
    float2 f0 = __half22float2(a.h[0]), g0 = __half22float2(b.h[0]);
    float2 f1 = __half22float2(a.h[1]), g1 = __half22float2(b.h[1]);
    float2 f2 = __half22float2(a.h[2]), g2 = __half22float2(b.h[2]);
    float2 f3 = __half22float2(a.h[3]), g3 = __half22float2(b.h[3]);
    float r = fmaxf(f0.x + g0.x, 0.f) * w0.x + fmaxf(f0.y + g0.y, 0.f) * w0.y
            + fmaxf(f1.x + g1.x, 0.f) * w0.z + fmaxf(f1.y + g1.y, 0.f) * w0.w
            + fmaxf(f2.x + g2.x, 0.f) * w1.x + fmaxf(f2.y + g2.y, 0.f) * w1.y
            + fmaxf(f3.x + g3.x, 0.f) * w1.z + fmaxf(f3.y + g3.y, 0.f) * w1.w;
    r += __shfl_down_sync(0xffffffffu, r, 4);
    r += __shfl_down_sync(0xffffffffu, r, 2);
    r += __shfl_down_sync(0xffffffffu, r, 1);
    if (l == 0) out[e] = r + bias;
}

// ---- PDL launch helper ----
template <typename F, typename... Args>
static void launch_pdl(F f, int grid, int block, cudaStream_t st, Args... args) {
    cudaLaunchConfig_t cfg = {};
    cfg.gridDim = dim3(grid);
    cfg.blockDim = dim3(block);
    cfg.stream = st;
    cudaLaunchAttribute at[1];
    at[0].id = cudaLaunchAttributeProgrammaticStreamSerialization;
    at[0].val.programmaticStreamSerializationAllowed = 1;
    cfg.attrs = at;
    cfg.numAttrs = 1;
    cudaLaunchKernelEx(&cfg, f, args...);
}

extern "C" void kernel_launch(void* const* d_in, const int* in_sizes, int n_in,
                              void* d_out, int out_size) {
    const float* feats    = (const float*)d_in[0];
    const float* W1       = (const float*)d_in[1];
    const float* b1       = (const float*)d_in[2];
    const float* W2       = (const float*)d_in[3];
    const float* b2       = (const float*)d_in[4];
    const float* W3       = (const float*)d_in[5];
    const float* b3       = (const float*)d_in[6];
    const float* W4       = (const float*)d_in[7];
    const float* b4       = (const float*)d_in[8];
    const int*   src_seq  = (const int*)d_in[9];
    const int*   dst_seq  = (const int*)d_in[10];
    const int*   src_next = (const int*)d_in[11];
    const int*   dst_next = (const int*)d_in[12];
    float* out = (float*)d_out;

    // use_temporal=False in the reference: only snapshot t = T-1 = 2 contributes.
    const float* x_last = feats   + (size_t)2 * N_NODES * IN_DIM;
    const int*   src    = src_seq + (size_t)2 * N_EDGES;
    const int*   dst    = dst_seq + (size_t)2 * N_EDGES;

    // One-time host resources (no device memory) for fork/join overlap.
    static cudaStream_t s_side = nullptr;
    static cudaEvent_t  s_fork = nullptr, s_join = nullptr;
    if (!s_side) {
        cudaStreamCreateWithFlags(&s_side, cudaStreamNonBlocking);
        cudaEventCreateWithFlags(&s_fork, cudaEventDisableTiming);
        cudaEventCreateWithFlags(&s_join, cudaEventDisableTiming);
    }

    k_deg<<<(N_EDGES / 4 + 255) / 256, 256>>>(src, dst);
    k_scan_local<<<NSCAN_BLOCKS, 256>>>();
    k_scan_add<<<(N_NODES + 255) / 256, 256>>>();

    // Fork AFTER scan_add: gemm1 (needs norm_out) overlaps csr_fill.
    cudaEventRecord(s_fork, 0);
    cudaStreamWaitEvent(s_side, s_fork, 0);
    k_gemm1_tc<<<NBLK_TC, 256, 0, s_side>>>(x_last, W1);
    cudaEventRecord(s_join, s_side);

    k_csr_fill<<<(N_EDGES / 4 + 255) / 256, 256>>>(src, dst);
    cudaStreamWaitEvent(0, s_join, 0);

    k_gather<<<(N_NODES * 32 + 255) / 256, 256>>>(b1, 0);
    launch_pdl(k_gemm2_tc, NBLK_TC, 256, (cudaStream_t)0, W2);
    k_gather<<<(N_NODES * 32 + 255) / 256, 256>>>(b2, 1);
    launch_pdl(k_post_tc, NBLK_TC, 256, (cudaStream_t)0, W3, b3);
    launch_pdl(k_score, (int)(((long long)N_EDGES * 8 + 255) / 256), 256, (cudaStream_t)0,
               src_next, dst_next, W4, b4, out);
}

// round 14
// speedup vs baseline: 1.0519x; 1.0519x over previous
#include <cuda_runtime.h>
#include <cuda_fp16.h>
#include <mma.h>

using namespace nvcuda;

#define N_NODES 100000
#define N_EDGES 1600000
#define IN_DIM  128
#define HID     64
#define SCAN_CHUNK 1024
#define NSCAN_BLOCKS ((N_NODES + SCAN_CHUNK - 1) / SCAN_CHUNK)   // 98
#define NBLK_TC ((N_NODES + 63) / 64)                             // 1563

// ---- scratch (static device globals; no runtime allocation) ----
__device__ __align__(16) __half g_y [(size_t)N_NODES * HID];  // per-layer GEMM output (gathered)
__device__ __align__(16) __half g_h [(size_t)N_NODES * HID];  // layer-1 activation
__device__ __align__(16) __half g_h2[(size_t)N_NODES * HID];  // layer-2 embedding
__device__ __align__(16) __half g_Hs[(size_t)N_NODES * HID];  // gathered by score
__device__ __align__(16) __half g_Hd[(size_t)N_NODES * HID];  // gathered by score
__device__ float g_norm_out[N_NODES];
__device__ float g_norm_in[N_NODES];
__device__ int   g_deg_out[N_NODES];   // zero at entry/exit of every run
__device__ int   g_deg_in[N_NODES];    // zero at entry/exit of every run
__device__ int   g_row_start[N_NODES];
__device__ int   g_cursor[N_NODES];    // after csr_fill: row END
__device__ int   g_bsum[NSCAN_BLOCKS];
__device__ int   g_csr[N_EDGES];

union HPack { uint2 u; __half2 h[2]; };
union HPack4 { uint4 u; __half2 h[4]; };

__device__ __forceinline__ void f4_to_h4(__half* d, float4 f) {
    HPack pk;
    pk.h[0] = __floats2half2_rn(f.x, f.y);
    pk.h[1] = __floats2half2_rn(f.z, f.w);
    *(uint2*)d = pk.u;
}

// ---- 1: degree histogram (4 edges/thread, int4 loads) ----
__global__ void k_deg(const int* __restrict__ src, const int* __restrict__ dst) {
    int i = blockIdx.x * blockDim.x + threadIdx.x;
    if (i < N_EDGES / 4) {
        int4 s4 = ((const int4*)src)[i];
        int4 d4 = ((const int4*)dst)[i];
        atomicAdd(&g_deg_out[s4.x], 1); atomicAdd(&g_deg_out[s4.y], 1);
        atomicAdd(&g_deg_out[s4.z], 1); atomicAdd(&g_deg_out[s4.w], 1);
        atomicAdd(&g_deg_in[d4.x], 1);  atomicAdd(&g_deg_in[d4.y], 1);
        atomicAdd(&g_deg_in[d4.z], 1);  atomicAdd(&g_deg_in[d4.w], 1);
    }
}

// ---- 2a: per-1024-chunk scan of deg_in ----
__global__ __launch_bounds__(256) void k_scan_local() {
    __shared__ int sh[256];
    int t = threadIdx.x;
    int base = blockIdx.x * SCAN_CHUNK + t * 4;
    int d0 = (base + 0 < N_NODES) ? g_deg_in[base + 0] : 0;
    int d1 = (base + 1 < N_NODES) ? g_deg_in[base + 1] : 0;
    int d2 = (base + 2 < N_NODES) ? g_deg_in[base + 2] : 0;
    int d3 = (base + 3 < N_NODES) ? g_deg_in[base + 3] : 0;
    int s = d0 + d1 + d2 + d3;
    sh[t] = s;
    __syncthreads();
    for (int off = 1; off < 256; off <<= 1) {
        int tmp = (t >= off) ? sh[t - off] : 0;
        __syncthreads();
        sh[t] += tmp;
        __syncthreads();
    }
    int excl = sh[t] - s;
    int r0 = excl, r1 = r0 + d0, r2 = r1 + d1, r3 = r2 + d2;
    if (base + 0 < N_NODES) g_row_start[base + 0] = r0;
    if (base + 1 < N_NODES) g_row_start[base + 1] = r1;
    if (base + 2 < N_NODES) g_row_start[base + 2] = r2;
    if (base + 3 < N_NODES) g_row_start[base + 3] = r3;
    if (t == 255) g_bsum[blockIdx.x] = sh[255];
}

// ---- 2b: finalize offsets + cursors + norms; zero counters for next run ----
__global__ __launch_bounds__(256) void k_scan_add() {
    __shared__ int orig[128], scn[128];
    int t = threadIdx.x;
    if (t < 128) {
        int v = (t < NSCAN_BLOCKS) ? g_bsum[t] : 0;
        orig[t] = v; scn[t] = v;
    }
    __syncthreads();
    for (int off = 1; off < 128; off <<= 1) {
        int tmp = (t < 128 && t >= off) ? scn[t - off] : 0;
        __syncthreads();
        if (t < 128) scn[t] += tmp;
        __syncthreads();
    }
    int i = blockIdx.x * blockDim.x + t;
    if (i < N_NODES) {
        int c = i >> 10;
        int dout = g_deg_out[i], din = g_deg_in[i];
        int r = g_row_start[i] + (scn[c] - orig[c]);
        g_row_start[i] = r;
        g_cursor[i] = r;
        g_norm_out[i] = rsqrtf(fmaxf((float)dout, 1.f));
        g_norm_in[i]  = rsqrtf(fmaxf((float)din,  1.f));
        g_deg_out[i] = 0;
        g_deg_in[i]  = 0;
    }
}

// ---- 2c: fill CSR (4 edges/thread; cursor[v] ends at row END) ----
__global__ void k_csr_fill(const int* __restrict__ src, const int* __restrict__ dst) {
    int i = blockIdx.x * blockDim.x + threadIdx.x;
    if (i < N_EDGES / 4) {
        int4 s4 = ((const int4*)src)[i];
        int4 d4 = ((const int4*)dst)[i];
        int p0 = atomicAdd(&g_cursor[d4.x], 1); g_csr[p0] = s4.x;
        int p1 = atomicAdd(&g_cursor[d4.y], 1); g_csr[p1] = s4.y;
        int p2 = atomicAdd(&g_cursor[d4.z], 1); g_csr[p2] = s4.z;
        int p3 = atomicAdd(&g_cursor[d4.w], 1); g_csr[p3] = s4.w;
    }
}

// ---- 3: y = x @ W1 (unscaled; norm_out applied in gather phase 0) -> fp16 ----
__global__ __launch_bounds__(256) void k_gemm1_tc(const float* __restrict__ x,
                                                  const float* __restrict__ W1) {
    __shared__ __align__(256) char sbuf[35840];
    half*  As = (half*)sbuf;                // [64][136]
    half*  Bs = (half*)(sbuf + 17408);      // [128][72]
    float* Cs = (float*)sbuf;               // [64][72] (alias)
    const int tid = threadIdx.x;
    const int wid = tid >> 5;
    const int v0 = blockIdx.x * 64;

    for (int i = tid; i < 128 * 16; i += 256) {
        int r = i >> 4, c4 = i & 15;
        f4_to_h4(Bs + r * 72 + c4 * 4, ((const float4*)W1)[i]);
    }
    for (int i = tid; i < 64 * 32; i += 256) {
        int r = i >> 5, c4 = i & 31;
        int v = v0 + r;
        float4 xv = (v < N_NODES) ? ((const float4*)(x + (size_t)v * IN_DIM))[c4]
                                  : make_float4(0.f, 0.f, 0.f, 0.f);
        f4_to_h4(As + r * 136 + c4 * 4, xv);
    }
    __syncthreads();

    const int wm = wid >> 1, wn = wid & 1;
    wmma::fragment<wmma::accumulator, 16, 16, 16, float> c0, c1;
    wmma::fill_fragment(c0, 0.f);
    wmma::fill_fragment(c1, 0.f);
    #pragma unroll
    for (int k0 = 0; k0 < 128; k0 += 16) {
        wmma::fragment<wmma::matrix_a, 16, 16, 16, half, wmma::row_major> a;
        wmma::fragment<wmma::matrix_b, 16, 16, 16, half, wmma::row_major> b0, b1;
        wmma::load_matrix_sync(a, As + wm * 16 * 136 + k0, 136);
        wmma::load_matrix_sync(b0, Bs + k0 * 72 + wn * 32, 72);
        wmma::load_matrix_sync(b1, Bs + k0 * 72 + wn * 32 + 16, 72);
        wmma::mma_sync(c0, a, b0, c0);
        wmma::mma_sync(c1, a, b1, c1);
    }
    __syncthreads();
    wmma::store_matrix_sync(Cs + wm * 16 * 72 + wn * 32,      c0, 72, wmma::mem_row_major);
    wmma::store_matrix_sync(Cs + wm * 16 * 72 + wn * 32 + 16, c1, 72, wmma::mem_row_major);
    __syncthreads();
    for (int i = tid; i < 64 * 16; i += 256) {
        int r = i >> 4, cq = i & 15;
        int v = v0 + r;
        if (v < N_NODES) {
            float4 f = ((const float4*)(Cs + r * 72))[cq];
            f4_to_h4(g_y + (size_t)v * HID + cq * 4, f);
        }
    }
}

// ---- 4/7: CSR gather, dual-edge half-warp form.
// phase 0: apply norm_out[src], +b1, relu -> g_h ; phase 1: plain sum, +b2 -> g_h2
__global__ __launch_bounds__(256) void k_gather(const float* __restrict__ bias, int phase) {
    int v    = (blockIdx.x * blockDim.x + threadIdx.x) >> 5;
    int lane = threadIdx.x & 31;
    if (v >= N_NODES) return;
    const int hw = lane >> 4;
    const int hl = lane & 15;
    __half* out = phase ? g_h2 : g_h;
    int beg = g_row_start[v];
    int end = g_cursor[v];
    const uint2* Y2 = (const uint2*)g_y;
    float a0 = 0.f, a1 = 0.f, a2 = 0.f, a3 = 0.f;
    int j = beg;
    for (; j + 15 < end; j += 16) {
        int base = j + hw * 8;
        #pragma unroll
        for (int k = 0; k < 8; k++) {
            int s = g_csr[base + k];
            HPack pk; pk.u = Y2[(size_t)s * 16 + hl];
            float2 f0 = __half22float2(pk.h[0]);
            float2 f1 = __half22float2(pk.h[1]);
            if (phase == 0) {
                float n = g_norm_out[s];
                a0 = fmaf(f0.x, n, a0); a1 = fmaf(f0.y, n, a1);
                a2 = fmaf(f1.x, n, a2); a3 = fmaf(f1.y, n, a3);
            } else {
                a0 += f0.x; a1 += f0.y; a2 += f1.x; a3 += f1.y;
            }
        }
    }
    for (; j < end; j += 2) {
        int idx = j + hw;
        if (idx < end) {
            int s = g_csr[idx];
            HPack pk; pk.u = Y2[(size_t)s * 16 + hl];
            float2 f0 = __half22float2(pk.h[0]);
            float2 f1 = __half22float2(pk.h[1]);
            if (phase == 0) {
                float n = g_norm_out[s];
                a0 = fmaf(f0.x, n, a0); a1 = fmaf(f0.y, n, a1);
                a2 = fmaf(f1.x, n, a2); a3 = fmaf(f1.y, n, a3);
            } else {
                a0 += f0.x; a1 += f0.y; a2 += f1.x; a3 += f1.y;
            }
        }
    }
    a0 += __shfl_xor_sync(0xffffffffu, a0, 16);
    a1 += __shfl_xor_sync(0xffffffffu, a1, 16);
    a2 += __shfl_xor_sync(0xffffffffu, a2, 16);
    a3 += __shfl_xor_sync(0xffffffffu, a3, 16);
    if (hw == 0) {
        float ni = g_norm_in[v];
        float4 bv = ((const float4*)bias)[hl];
        float r0 = a0 * ni + bv.x;
        float r1 = a1 * ni + bv.y;
        float r2 = a2 * ni + bv.z;
        float r3 = a3 * ni + bv.w;
        if (phase == 0) {
            r0 = fmaxf(r0, 0.f); r1 = fmaxf(r1, 0.f);
            r2 = fmaxf(r2, 0.f); r3 = fmaxf(r3, 0.f);
        }
        HPack pk;
        pk.h[0] = __floats2half2_rn(r0, r1);
        pk.h[1] = __floats2half2_rn(r2, r3);
        ((uint2*)(out + (size_t)v * HID))[hl] = pk.u;
    }
}

// ---- 6: y = (h @ W2) * norm_out -> fp16. PDL: W2 preamble, grid-dep sync ----
__global__ __launch_bounds__(256) void k_gemm2_tc(const float* __restrict__ W2) {
    __shared__ __align__(256) char sbuf[18432];
    half*  As = (half*)sbuf;                // [64][72]
    half*  Bs = (half*)(sbuf + 9216);       // [64][72]
    float* Cs = (float*)sbuf;               // [64][72] (alias)
    const int tid = threadIdx.x;
    const int wid = tid >> 5;
    const int v0 = blockIdx.x * 64;

    for (int i = tid; i < 64 * 16; i += 256) {            // W2 (input): dep-free preamble
        int r = i >> 4, c4 = i & 15;
        f4_to_h4(Bs + r * 72 + c4 * 4, ((const float4*)W2)[i]);
    }
    cudaGridDependencySynchronize();                      // wait for gather0's g_h
    for (int i = tid; i < 64 * 8; i += 256) {
        int r = i >> 3, c8 = i & 7;
        int v = v0 + r;
        uint4 hv = (v < N_NODES) ? ((const uint4*)(g_h + (size_t)v * HID))[c8]
                                 : make_uint4(0u, 0u, 0u, 0u);
        *(uint4*)(As + r * 72 + c8 * 8) = hv;
    }
    __syncthreads();

    const int wm = wid >> 1, wn = wid & 1;
    wmma::fragment<wmma::accumulator, 16, 16, 16, float> c0, c1;
    wmma::fill_fragment(c0, 0.f);
    wmma::fill_fragment(c1, 0.f);
    #pragma unroll
    for (int k0 = 0; k0 < 64; k0 += 16) {
        wmma::fragment<wmma::matrix_a, 16, 16, 16, half, wmma::row_major> a;
        wmma::fragment<wmma::matrix_b, 16, 16, 16, half, wmma::row_major> b0, b1;
        wmma::load_matrix_sync(a, As + wm * 16 * 72 + k0, 72);
        wmma::load_matrix_sync(b0, Bs + k0 * 72 + wn * 32, 72);
        wmma::load_matrix_sync(b1, Bs + k0 * 72 + wn * 32 + 16, 72);
        wmma::mma_sync(c0, a, b0, c0);
        wmma::mma_sync(c1, a, b1, c1);
    }
    __syncthreads();
    wmma::store_matrix_sync(Cs + wm * 16 * 72 + wn * 32,      c0, 72, wmma::mem_row_major);
    wmma::store_matrix_sync(Cs + wm * 16 * 72 + wn * 32 + 16, c1, 72, wmma::mem_row_major);
    __syncthreads();
    for (int i = tid; i < 64 * 16; i += 256) {
        int r = i >> 4, cq = i & 15;
        int v = v0 + r;
        if (v < N_NODES) {
            float n = g_norm_out[v];
            float4 f = ((const float4*)(Cs + r * 72))[cq];
            f.x *= n; f.y *= n; f.z *= n; f.w *= n;
            f4_to_h4(g_y + (size_t)v * HID + cq * 4, f);
        }
    }
}

// ---- 8: [Hs|Hd] = h2 @ [W3top|W3bot] (+b3 on Hs) -> fp16. PDL preamble on W3 ----
__global__ __launch_bounds__(256) void k_post_tc(const float* __restrict__ W3,
                                                 const float* __restrict__ b3v) {
    __shared__ __align__(256) char sbuf[34816];
    half*  As = (half*)sbuf;                // [64][72]
    half*  Bs = (half*)(sbuf + 9216);       // [64][136]
    float* Cs = (float*)sbuf;               // [64][136] (alias)
    const int tid = threadIdx.x;
    const int wid = tid >> 5;
    const int v0 = blockIdx.x * 64;

    // B[k][n] = n<64 ? W3[k][n] : W3[64+k][n-64]  (input: dep-free preamble)
    for (int i = tid; i < 64 * 32; i += 256) {
        int k = i >> 5, c4 = i & 31;
        int n = c4 * 4;
        const float4* srcp = (n < 64)
            ? (const float4*)(W3 + (size_t)k * 64 + n)
            : (const float4*)(W3 + (size_t)(64 + k) * 64 + (n - 64));
        f4_to_h4(Bs + k * 136 + n, *srcp);
    }
    cudaGridDependencySynchronize();                      // wait for gather1's g_h2
    for (int i = tid; i < 64 * 8; i += 256) {
        int r = i >> 3, c8 = i & 7;
        int v = v0 + r;
        uint4 hv = (v < N_NODES) ? ((const uint4*)(g_h2 + (size_t)v * HID))[c8]
                                 : make_uint4(0u, 0u, 0u, 0u);
        *(uint4*)(As + r * 72 + c8 * 8) = hv;
    }
    __syncthreads();

    const int wm = wid >> 2, wn = wid & 3;
    wmma::fragment<wmma::accumulator, 16, 16, 16, float> c00, c01, c10, c11;
    wmma::fill_fragment(c00, 0.f); wmma::fill_fragment(c01, 0.f);
    wmma::fill_fragment(c10, 0.f); wmma::fill_fragment(c11, 0.f);
    #pragma unroll
    for (int k0 = 0; k0 < 64; k0 += 16) {
        wmma::fragment<wmma::matrix_a, 16, 16, 16, half, wmma::row_major> a0, a1;
        wmma::fragment<wmma::matrix_b, 16, 16, 16, half, wmma::row_major> b0, b1;
        wmma::load_matrix_sync(a0, As + (wm * 32)      * 72 + k0, 72);
        wmma::load_matrix_sync(a1, As + (wm * 32 + 16) * 72 + k0, 72);
        wmma::load_matrix_sync(b0, Bs + k0 * 136 + wn * 32,      136);
        wmma::load_matrix_sync(b1, Bs + k0 * 136 + wn * 32 + 16, 136);
        wmma::mma_sync(c00, a0, b0, c00);
        wmma::mma_sync(c01, a0, b1, c01);
        wmma::mma_sync(c10, a1, b0, c10);
        wmma::mma_sync(c11, a1, b1, c11);
    }
    __syncthreads();
    wmma::store_matrix_sync(Cs + (wm * 32)      * 136 + wn * 32,      c00, 136, wmma::mem_row_major);
    wmma::store_matrix_sync(Cs + (wm * 32)      * 136 + wn * 32 + 16, c01, 136, wmma::mem_row_major);
    wmma::store_matrix_sync(Cs + (wm * 32 + 16) * 136 + wn * 32,      c10, 136, wmma::mem_row_major);
    wmma::store_matrix_sync(Cs + (wm * 32 + 16) * 136 + wn * 32 + 16, c11, 136, wmma::mem_row_major);
    __syncthreads();
    for (int i = tid; i < 64 * 32; i += 256) {
        int r = i >> 5, c4 = i & 31;
        int col = c4 * 4;
        int v = v0 + r;
        if (v < N_NODES) {
            float4 f = *(const float4*)(Cs + r * 136 + col);
            if (col < 64) {
                float4 b = *(const float4*)(b3v + col);
                f.x += b.x; f.y += b.y; f.z += b.z; f.w += b.w;
                f4_to_h4(g_Hs + (size_t)v * HID + col, f);
            } else {
                f4_to_h4(g_Hd + (size_t)v * HID + (col - 64), f);
            }
        }
    }
}

// ---- 9: per-edge score. PDL preamble: edge indices + W4 (inputs, dep-free) ----
__global__ __launch_bounds__(256) void k_score(const int* __restrict__ sn,
                                               const int* __restrict__ dn,
                                               const float* __restrict__ W4,
                                               const float* __restrict__ b4,
                                               float* __restrict__ out) {
    long long t = (long long)blockIdx.x * blockDim.x + threadIdx.x;
    int e = (int)(t >> 3);
    int l = (int)t & 7;
    if (e >= N_EDGES) {
        cudaGridDependencySynchronize();
        return;
    }
    int s = __ldg(&sn[e]);
    int d = __ldg(&dn[e]);
    float4 w0 = __ldg((const float4*)W4 + 2 * l);
    float4 w1 = __ldg((const float4*)W4 + 2 * l + 1);
    float bias = __ldg(&b4[0]);
    cudaGridDependencySynchronize();                      // wait for Hs/Hd
    HPack4 a, b;
    a.u = ((const uint4*)(g_Hs + (size_t)s * HID))[l];
    b.u = ((const uint4*)(g_Hd + (size_t)d * HID))[l];
    float2 f0 = __half22float2(a.h[0]), g0 = __half22float2(b.h[0]);
    float2 f1 = __half22float2(a.h[1]), g1 = __half22float2(b.h[1]);
    float2 f2 = __half22float2(a.h[2]), g2 = __half22float2(b.h[2]);
    float2 f3 = __half22float2(a.h[3]), g3 = __half22float2(b.h[3]);
    float r = fmaxf(f0.x + g0.x, 0.f) * w0.x + fmaxf(f0.y + g0.y, 0.f) * w0.y
            + fmaxf(f1.x + g1.x, 0.f) * w0.z + fmaxf(f1.y + g1.y, 0.f) * w0.w
            + fmaxf(f2.x + g2.x, 0.f) * w1.x + fmaxf(f2.y + g2.y, 0.f) * w1.y
            + fmaxf(f3.x + g3.x, 0.f) * w1.z + fmaxf(f3.y + g3.y, 0.f) * w1.w;
    r += __shfl_down_sync(0xffffffffu, r, 4);
    r += __shfl_down_sync(0xffffffffu, r, 2);
    r += __shfl_down_sync(0xffffffffu, r, 1);
    if (l == 0) out[e] = r + bias;
}

// ---- PDL launch helper ----
template <typename F, typename... Args>
static void launch_pdl(F f, int grid, int block, cudaStream_t st, Args... args) {
    cudaLaunchConfig_t cfg = {};
    cfg.gridDim = dim3(grid);
    cfg.blockDim = dim3(block);
    cfg.stream = st;
    cudaLaunchAttribute at[1];
    at[0].id = cudaLaunchAttributeProgrammaticStreamSerialization;
    at[0].val.programmaticStreamSerializationAllowed = 1;
    cfg.attrs = at;
    cfg.numAttrs = 1;
    cudaLaunchKernelEx(&cfg, f, args...);
}

extern "C" void kernel_launch(void* const* d_in, const int* in_sizes, int n_in,
                              void* d_out, int out_size) {
    const float* feats    = (const float*)d_in[0];
    const float* W1       = (const float*)d_in[1];
    const float* b1       = (const float*)d_in[2];
    const float* W2       = (const float*)d_in[3];
    const float* b2       = (const float*)d_in[4];
    const float* W3       = (const float*)d_in[5];
    const float* b3       = (const float*)d_in[6];
    const float* W4       = (const float*)d_in[7];
    const float* b4       = (const float*)d_in[8];
    const int*   src_seq  = (const int*)d_in[9];
    const int*   dst_seq  = (const int*)d_in[10];
    const int*   src_next = (const int*)d_in[11];
    const int*   dst_next = (const int*)d_in[12];
    float* out = (float*)d_out;

    // use_temporal=False in the reference: only snapshot t = T-1 = 2 contributes.
    const float* x_last = feats   + (size_t)2 * N_NODES * IN_DIM;
    const int*   src    = src_seq + (size_t)2 * N_EDGES;
    const int*   dst    = dst_seq + (size_t)2 * N_EDGES;

    // One-time host resources (no device memory) for fork/join overlap.
    static cudaStream_t s_side = nullptr;
    static cudaEvent_t  s_fork = nullptr, s_join = nullptr;
    if (!s_side) {
        cudaStreamCreateWithFlags(&s_side, cudaStreamNonBlocking);
        cudaEventCreateWithFlags(&s_fork, cudaEventDisableTiming);
        cudaEventCreateWithFlags(&s_join, cudaEventDisableTiming);
    }

    // Fork EARLY: gemm1 (unscaled, independent of graph) spans the whole CSR build.
    cudaEventRecord(s_fork, 0);
    cudaStreamWaitEvent(s_side, s_fork, 0);
    k_gemm1_tc<<<NBLK_TC, 256, 0, s_side>>>(x_last, W1);
    cudaEventRecord(s_join, s_side);

    k_deg<<<(N_EDGES / 4 + 255) / 256, 256>>>(src, dst);
    k_scan_local<<<NSCAN_BLOCKS, 256>>>();
    k_scan_add<<<(N_NODES + 255) / 256, 256>>>();
    k_csr_fill<<<(N_EDGES / 4 + 255) / 256, 256>>>(src, dst);

    cudaStreamWaitEvent(0, s_join, 0);

    k_gather<<<(N_NODES * 32 + 255) / 256, 256>>>(b1, 0);
    launch_pdl(k_gemm2_tc, NBLK_TC, 256, (cudaStream_t)0, W2);
    k_gather<<<(N_NODES * 32 + 255) / 256, 256>>>(b2, 1);
    launch_pdl(k_post_tc, NBLK_TC, 256, (cudaStream_t)0, W3, b3);
    launch_pdl(k_score, (int)(((long long)N_EDGES * 8 + 255) / 256), 256, (cudaStream_t)0,
               src_next, dst_next, W4, b4, out);
}

// round 15
// speedup vs baseline: 1.0795x; 1.0262x over previous
#include <cuda_runtime.h>
#include <cuda_fp16.h>
#include <mma.h>

using namespace nvcuda;

#define N_NODES 100000
#define N_EDGES 1600000
#define IN_DIM  128
#define HID     64
#define SCAN_CHUNK 1024
#define NSCAN_BLOCKS ((N_NODES + SCAN_CHUNK - 1) / SCAN_CHUNK)   // 98
#define NBLK_TC ((N_NODES + 63) / 64)                             // 1563

// ---- scratch (static device globals; no runtime allocation) ----
__device__ __align__(16) __half g_y [(size_t)N_NODES * HID];
__device__ __align__(16) __half g_h [(size_t)N_NODES * HID];
__device__ __align__(16) __half g_h2[(size_t)N_NODES * HID];
__device__ __align__(16) __half g_Hs[(size_t)N_NODES * HID];
__device__ __align__(16) __half g_Hd[(size_t)N_NODES * HID];
__device__ __align__(16) __half g_W1h[IN_DIM * 72];    // W1 padded fp16 smem image
__device__ __align__(16) __half g_W2h[HID * 72];       // W2 padded
__device__ __align__(16) __half g_W3h[HID * 136];      // [W3top|W3bot] combined, padded
__device__ float g_norm_out[N_NODES];
__device__ float g_norm_in[N_NODES];
__device__ int   g_deg_out[N_NODES];   // zero at entry/exit of every run
__device__ int   g_deg_in[N_NODES];    // zero at entry/exit of every run
__device__ int   g_row_start[N_NODES];
__device__ int   g_cursor[N_NODES];    // after csr_fill: row END
__device__ int   g_bsum[NSCAN_BLOCKS];
__device__ int   g_csr[N_EDGES];

union HPack { uint2 u; __half2 h[2]; };
union HPack4 { uint4 u; __half2 h[4]; };

__device__ __forceinline__ void f4_to_h4(__half* d, float4 f) {
    HPack pk;
    pk.h[0] = __floats2half2_rn(f.x, f.y);
    pk.h[1] = __floats2half2_rn(f.z, f.w);
    *(uint2*)d = pk.u;
}

// ---- 0: one-time weight conversion to padded fp16 images ----
__global__ void k_prep(const float* __restrict__ W1, const float* __restrict__ W2,
                       const float* __restrict__ W3) {
    int i = blockIdx.x * blockDim.x + threadIdx.x;
    // W1: 128x64 -> [128][72]
    if (i < IN_DIM * HID) {
        int r = i >> 6, c = i & 63;
        g_W1h[r * 72 + c] = __float2half_rn(W1[i]);
    }
    // W2: 64x64 -> [64][72]
    int j = i - IN_DIM * HID;
    if (j >= 0 && j < HID * HID) {
        int r = j >> 6, c = j & 63;
        g_W2h[r * 72 + c] = __float2half_rn(W2[j]);
    }
    // W3 combined: B[k][n] = n<64 ? W3[k][n] : W3[64+k][n-64] -> [64][136]
    int k = i - IN_DIM * HID - HID * HID;
    if (k >= 0 && k < HID * 128) {
        int r = k >> 7, n = k & 127;
        float v = (n < 64) ? W3[(size_t)r * 64 + n] : W3[(size_t)(64 + r) * 64 + (n - 64)];
        g_W3h[r * 136 + n] = __float2half_rn(v);
    }
}

// ---- 1: degree histogram (4 edges/thread, int4 loads) ----
__global__ void k_deg(const int* __restrict__ src, const int* __restrict__ dst) {
    int i = blockIdx.x * blockDim.x + threadIdx.x;
    if (i < N_EDGES / 4) {
        int4 s4 = ((const int4*)src)[i];
        int4 d4 = ((const int4*)dst)[i];
        atomicAdd(&g_deg_out[s4.x], 1); atomicAdd(&g_deg_out[s4.y], 1);
        atomicAdd(&g_deg_out[s4.z], 1); atomicAdd(&g_deg_out[s4.w], 1);
        atomicAdd(&g_deg_in[d4.x], 1);  atomicAdd(&g_deg_in[d4.y], 1);
        atomicAdd(&g_deg_in[d4.z], 1);  atomicAdd(&g_deg_in[d4.w], 1);
    }
}

// ---- 2a: per-1024-chunk scan of deg_in ----
__global__ __launch_bounds__(256) void k_scan_local() {
    __shared__ int sh[256];
    int t = threadIdx.x;
    int base = blockIdx.x * SCAN_CHUNK + t * 4;
    int d0 = (base + 0 < N_NODES) ? g_deg_in[base + 0] : 0;
    int d1 = (base + 1 < N_NODES) ? g_deg_in[base + 1] : 0;
    int d2 = (base + 2 < N_NODES) ? g_deg_in[base + 2] : 0;
    int d3 = (base + 3 < N_NODES) ? g_deg_in[base + 3] : 0;
    int s = d0 + d1 + d2 + d3;
    sh[t] = s;
    __syncthreads();
    for (int off = 1; off < 256; off <<= 1) {
        int tmp = (t >= off) ? sh[t - off] : 0;
        __syncthreads();
        sh[t] += tmp;
        __syncthreads();
    }
    int excl = sh[t] - s;
    int r0 = excl, r1 = r0 + d0, r2 = r1 + d1, r3 = r2 + d2;
    if (base + 0 < N_NODES) g_row_start[base + 0] = r0;
    if (base + 1 < N_NODES) g_row_start[base + 1] = r1;
    if (base + 2 < N_NODES) g_row_start[base + 2] = r2;
    if (base + 3 < N_NODES) g_row_start[base + 3] = r3;
    if (t == 255) g_bsum[blockIdx.x] = sh[255];
}

// ---- 2b: finalize offsets + cursors + norms; zero counters for next run ----
__global__ __launch_bounds__(256) void k_scan_add() {
    __shared__ int orig[128], scn[128];
    int t = threadIdx.x;
    if (t < 128) {
        int v = (t < NSCAN_BLOCKS) ? g_bsum[t] : 0;
        orig[t] = v; scn[t] = v;
    }
    __syncthreads();
    for (int off = 1; off < 128; off <<= 1) {
        int tmp = (t < 128 && t >= off) ? scn[t - off] : 0;
        __syncthreads();
        if (t < 128) scn[t] += tmp;
        __syncthreads();
    }
    int i = blockIdx.x * blockDim.x + t;
    if (i < N_NODES) {
        int c = i >> 10;
        int dout = g_deg_out[i], din = g_deg_in[i];
        int r = g_row_start[i] + (scn[c] - orig[c]);
        g_row_start[i] = r;
        g_cursor[i] = r;
        g_norm_out[i] = rsqrtf(fmaxf((float)dout, 1.f));
        g_norm_in[i]  = rsqrtf(fmaxf((float)din,  1.f));
        g_deg_out[i] = 0;
        g_deg_in[i]  = 0;
    }
}

// ---- 2c: fill CSR (4 edges/thread; cursor[v] ends at row END) ----
__global__ void k_csr_fill(const int* __restrict__ src, const int* __restrict__ dst) {
    int i = blockIdx.x * blockDim.x + threadIdx.x;
    if (i < N_EDGES / 4) {
        int4 s4 = ((const int4*)src)[i];
        int4 d4 = ((const int4*)dst)[i];
        int p0 = atomicAdd(&g_cursor[d4.x], 1); g_csr[p0] = s4.x;
        int p1 = atomicAdd(&g_cursor[d4.y], 1); g_csr[p1] = s4.y;
        int p2 = atomicAdd(&g_cursor[d4.z], 1); g_csr[p2] = s4.z;
        int p3 = atomicAdd(&g_cursor[d4.w], 1); g_csr[p3] = s4.w;
    }
}

// ---- 3: y = x @ W1 (unscaled; norm_out applied in gather phase 0) -> fp16 ----
__global__ __launch_bounds__(256) void k_gemm1_tc(const float* __restrict__ x) {
    __shared__ __align__(256) char sbuf[35840];
    half*  As = (half*)sbuf;                // [64][136]
    half*  Bs = (half*)(sbuf + 17408);      // [128][72]
    float* Cs = (float*)sbuf;               // [64][72] (alias)
    const int tid = threadIdx.x;
    const int wid = tid >> 5;
    const int v0 = blockIdx.x * 64;

    for (int i = tid; i < IN_DIM * 72 / 8; i += 256)      // W1h: linear uint4 copy
        ((uint4*)Bs)[i] = ((const uint4*)g_W1h)[i];
    for (int i = tid; i < 64 * 32; i += 256) {
        int r = i >> 5, c4 = i & 31;
        int v = v0 + r;
        float4 xv = (v < N_NODES) ? ((const float4*)(x + (size_t)v * IN_DIM))[c4]
                                  : make_float4(0.f, 0.f, 0.f, 0.f);
        f4_to_h4(As + r * 136 + c4 * 4, xv);
    }
    __syncthreads();

    const int wm = wid >> 1, wn = wid & 1;
    wmma::fragment<wmma::accumulator, 16, 16, 16, float> c0, c1;
    wmma::fill_fragment(c0, 0.f);
    wmma::fill_fragment(c1, 0.f);
    #pragma unroll
    for (int k0 = 0; k0 < 128; k0 += 16) {
        wmma::fragment<wmma::matrix_a, 16, 16, 16, half, wmma::row_major> a;
        wmma::fragment<wmma::matrix_b, 16, 16, 16, half, wmma::row_major> b0, b1;
        wmma::load_matrix_sync(a, As + wm * 16 * 136 + k0, 136);
        wmma::load_matrix_sync(b0, Bs + k0 * 72 + wn * 32, 72);
        wmma::load_matrix_sync(b1, Bs + k0 * 72 + wn * 32 + 16, 72);
        wmma::mma_sync(c0, a, b0, c0);
        wmma::mma_sync(c1, a, b1, c1);
    }
    __syncthreads();
    wmma::store_matrix_sync(Cs + wm * 16 * 72 + wn * 32,      c0, 72, wmma::mem_row_major);
    wmma::store_matrix_sync(Cs + wm * 16 * 72 + wn * 32 + 16, c1, 72, wmma::mem_row_major);
    __syncthreads();
    for (int i = tid; i < 64 * 16; i += 256) {
        int r = i >> 4, cq = i & 15;
        int v = v0 + r;
        if (v < N_NODES) {
            float4 f = ((const float4*)(Cs + r * 72))[cq];
            f4_to_h4(g_y + (size_t)v * HID + cq * 4, f);
        }
    }
}

// ---- 4/7: CSR gather, dual-edge half-warp form.
// phase 0: apply norm_out[src], +b1, relu -> g_h ; phase 1: plain sum, +b2 -> g_h2
__global__ __launch_bounds__(256) void k_gather(const float* __restrict__ bias, int phase) {
    int v    = (blockIdx.x * blockDim.x + threadIdx.x) >> 5;
    int lane = threadIdx.x & 31;
    if (v >= N_NODES) return;
    const int hw = lane >> 4;
    const int hl = lane & 15;
    __half* out = phase ? g_h2 : g_h;
    int beg = g_row_start[v];
    int end = g_cursor[v];
    const uint2* Y2 = (const uint2*)g_y;
    float a0 = 0.f, a1 = 0.f, a2 = 0.f, a3 = 0.f;
    int j = beg;
    for (; j + 15 < end; j += 16) {
        int base = j + hw * 8;
        #pragma unroll
        for (int k = 0; k < 8; k++) {
            int s = g_csr[base + k];
            HPack pk; pk.u = Y2[(size_t)s * 16 + hl];
            float2 f0 = __half22float2(pk.h[0]);
            float2 f1 = __half22float2(pk.h[1]);
            if (phase == 0) {
                float n = g_norm_out[s];
                a0 = fmaf(f0.x, n, a0); a1 = fmaf(f0.y, n, a1);
                a2 = fmaf(f1.x, n, a2); a3 = fmaf(f1.y, n, a3);
            } else {
                a0 += f0.x; a1 += f0.y; a2 += f1.x; a3 += f1.y;
            }
        }
    }
    for (; j < end; j += 2) {
        int idx = j + hw;
        if (idx < end) {
            int s = g_csr[idx];
            HPack pk; pk.u = Y2[(size_t)s * 16 + hl];
            float2 f0 = __half22float2(pk.h[0]);
            float2 f1 = __half22float2(pk.h[1]);
            if (phase == 0) {
                float n = g_norm_out[s];
                a0 = fmaf(f0.x, n, a0); a1 = fmaf(f0.y, n, a1);
                a2 = fmaf(f1.x, n, a2); a3 = fmaf(f1.y, n, a3);
            } else {
                a0 += f0.x; a1 += f0.y; a2 += f1.x; a3 += f1.y;
            }
        }
    }
    a0 += __shfl_xor_sync(0xffffffffu, a0, 16);
    a1 += __shfl_xor_sync(0xffffffffu, a1, 16);
    a2 += __shfl_xor_sync(0xffffffffu, a2, 16);
    a3 += __shfl_xor_sync(0xffffffffu, a3, 16);
    if (hw == 0) {
        float ni = g_norm_in[v];
        float4 bv = ((const float4*)bias)[hl];
        float r0 = a0 * ni + bv.x;
        float r1 = a1 * ni + bv.y;
        float r2 = a2 * ni + bv.z;
        float r3 = a3 * ni + bv.w;
        if (phase == 0) {
            r0 = fmaxf(r0, 0.f); r1 = fmaxf(r1, 0.f);
            r2 = fmaxf(r2, 0.f); r3 = fmaxf(r3, 0.f);
        }
        HPack pk;
        pk.h[0] = __floats2half2_rn(r0, r1);
        pk.h[1] = __floats2half2_rn(r2, r3);
        ((uint2*)(out + (size_t)v * HID))[hl] = pk.u;
    }
}

// ---- 6: y = (h @ W2) * norm_out -> fp16. PDL: W2h preamble copy, grid-dep sync ----
__global__ __launch_bounds__(256) void k_gemm2_tc() {
    __shared__ __align__(256) char sbuf[18432];
    half*  As = (half*)sbuf;                // [64][72]
    half*  Bs = (half*)(sbuf + 9216);       // [64][72]
    float* Cs = (float*)sbuf;               // [64][72] (alias)
    const int tid = threadIdx.x;
    const int wid = tid >> 5;
    const int v0 = blockIdx.x * 64;

    for (int i = tid; i < HID * 72 / 8; i += 256)         // W2h: preamble uint4 copy
        ((uint4*)Bs)[i] = ((const uint4*)g_W2h)[i];
    cudaGridDependencySynchronize();                      // wait for gather0's g_h
    for (int i = tid; i < 64 * 8; i += 256) {
        int r = i >> 3, c8 = i & 7;
        int v = v0 + r;
        uint4 hv = (v < N_NODES) ? ((const uint4*)(g_h + (size_t)v * HID))[c8]
                                 : make_uint4(0u, 0u, 0u, 0u);
        *(uint4*)(As + r * 72 + c8 * 8) = hv;
    }
    __syncthreads();

    const int wm = wid >> 1, wn = wid & 1;
    wmma::fragment<wmma::accumulator, 16, 16, 16, float> c0, c1;
    wmma::fill_fragment(c0, 0.f);
    wmma::fill_fragment(c1, 0.f);
    #pragma unroll
    for (int k0 = 0; k0 < 64; k0 += 16) {
        wmma::fragment<wmma::matrix_a, 16, 16, 16, half, wmma::row_major> a;
        wmma::fragment<wmma::matrix_b, 16, 16, 16, half, wmma::row_major> b0, b1;
        wmma::load_matrix_sync(a, As + wm * 16 * 72 + k0, 72);
        wmma::load_matrix_sync(b0, Bs + k0 * 72 + wn * 32, 72);
        wmma::load_matrix_sync(b1, Bs + k0 * 72 + wn * 32 + 16, 72);
        wmma::mma_sync(c0, a, b0, c0);
        wmma::mma_sync(c1, a, b1, c1);
    }
    __syncthreads();
    wmma::store_matrix_sync(Cs + wm * 16 * 72 + wn * 32,      c0, 72, wmma::mem_row_major);
    wmma::store_matrix_sync(Cs + wm * 16 * 72 + wn * 32 + 16, c1, 72, wmma::mem_row_major);
    __syncthreads();
    for (int i = tid; i < 64 * 16; i += 256) {
        int r = i >> 4, cq = i & 15;
        int v = v0 + r;
        if (v < N_NODES) {
            float n = g_norm_out[v];
            float4 f = ((const float4*)(Cs + r * 72))[cq];
            f.x *= n; f.y *= n; f.z *= n; f.w *= n;
            f4_to_h4(g_y + (size_t)v * HID + cq * 4, f);
        }
    }
}

// ---- 8: [Hs|Hd] = h2 @ W3h (+b3 on Hs) -> fp16. PDL: W3h preamble copy ----
__global__ __launch_bounds__(256) void k_post_tc(const float* __restrict__ b3v) {
    __shared__ __align__(256) char sbuf[34816];
    half*  As = (half*)sbuf;                // [64][72]
    half*  Bs = (half*)(sbuf + 9216);       // [64][136]
    float* Cs = (float*)sbuf;               // [64][136] (alias)
    const int tid = threadIdx.x;
    const int wid = tid >> 5;
    const int v0 = blockIdx.x * 64;

    for (int i = tid; i < HID * 136 / 8; i += 256)        // W3h: preamble uint4 copy
        ((uint4*)Bs)[i] = ((const uint4*)g_W3h)[i];
    cudaGridDependencySynchronize();                      // wait for gather1's g_h2
    for (int i = tid; i < 64 * 8; i += 256) {
        int r = i >> 3, c8 = i & 7;
        int v = v0 + r;
        uint4 hv = (v < N_NODES) ? ((const uint4*)(g_h2 + (size_t)v * HID))[c8]
                                 : make_uint4(0u, 0u, 0u, 0u);
        *(uint4*)(As + r * 72 + c8 * 8) = hv;
    }
    __syncthreads();

    const int wm = wid >> 2, wn = wid & 3;
    wmma::fragment<wmma::accumulator, 16, 16, 16, float> c00, c01, c10, c11;
    wmma::fill_fragment(c00, 0.f); wmma::fill_fragment(c01, 0.f);
    wmma::fill_fragment(c10, 0.f); wmma::fill_fragment(c11, 0.f);
    #pragma unroll
    for (int k0 = 0; k0 < 64; k0 += 16) {
        wmma::fragment<wmma::matrix_a, 16, 16, 16, half, wmma::row_major> a0, a1;
        wmma::fragment<wmma::matrix_b, 16, 16, 16, half, wmma::row_major> b0, b1;
        wmma::load_matrix_sync(a0, As + (wm * 32)      * 72 + k0, 72);
        wmma::load_matrix_sync(a1, As + (wm * 32 + 16) * 72 + k0, 72);
        wmma::load_matrix_sync(b0, Bs + k0 * 136 + wn * 32,      136);
        wmma::load_matrix_sync(b1, Bs + k0 * 136 + wn * 32 + 16, 136);
        wmma::mma_sync(c00, a0, b0, c00);
        wmma::mma_sync(c01, a0, b1, c01);
        wmma::mma_sync(c10, a1, b0, c10);
        wmma::mma_sync(c11, a1, b1, c11);
    }
    __syncthreads();
    wmma::store_matrix_sync(Cs + (wm * 32)      * 136 + wn * 32,      c00, 136, wmma::mem_row_major);
    wmma::store_matrix_sync(Cs + (wm * 32)      * 136 + wn * 32 + 16, c01, 136, wmma::mem_row_major);
    wmma::store_matrix_sync(Cs + (wm * 32 + 16) * 136 + wn * 32,      c10, 136, wmma::mem_row_major);
    wmma::store_matrix_sync(Cs + (wm * 32 + 16) * 136 + wn * 32 + 16, c11, 136, wmma::mem_row_major);
    __syncthreads();
    for (int i = tid; i < 64 * 32; i += 256) {
        int r = i >> 5, c4 = i & 31;
        int col = c4 * 4;
        int v = v0 + r;
        if (v < N_NODES) {
            float4 f = *(const float4*)(Cs + r * 136 + col);
            if (col < 64) {
                float4 b = *(const float4*)(b3v + col);
                f.x += b.x; f.y += b.y; f.z += b.z; f.w += b.w;
                f4_to_h4(g_Hs + (size_t)v * HID + col, f);
            } else {
                f4_to_h4(g_Hd + (size_t)v * HID + (col - 64), f);
            }
        }
    }
}

// ---- 9: per-edge score. PDL preamble: edge indices + W4 (inputs, dep-free) ----
__global__ __launch_bounds__(256) void k_score(const int* __restrict__ sn,
                                               const int* __restrict__ dn,
                                               const float* __restrict__ W4,
                                               const float* __restrict__ b4,
                                               float* __restrict__ out) {
    long long t = (long long)blockIdx.x * blockDim.x + threadIdx.x;
    int e = (int)(t >> 3);
    int l = (int)t & 7;
    if (e >= N_EDGES) {
        cudaGridDependencySynchronize();
        return;
    }
    int s = __ldg(&sn[e]);
    int d = __ldg(&dn[e]);
    float4 w0 = __ldg((const float4*)W4 + 2 * l);
    float4 w1 = __ldg((const float4*)W4 + 2 * l + 1);
    float bias = __ldg(&b4[0]);
    cudaGridDependencySynchronize();                      // wait for Hs/Hd
    HPack4 a, b;
    a.u = ((const uint4*)(g_Hs + (size_t)s * HID))[l];
    b.u = ((const uint4*)(g_Hd + (size_t)d * HID))[l];
    float2 f0 = __half22float2(a.h[0]), g0 = __half22float2(b.h[0]);
    float2 f1 = __half22float2(a.h[1]), g1 = __half22float2(b.h[1]);
    float2 f2 = __half22float2(a.h[2]), g2 = __half22float2(b.h[2]);
    float2 f3 = __half22float2(a.h[3]), g3 = __half22float2(b.h[3]);
    float r = fmaxf(f0.x + g0.x, 0.f) * w0.x + fmaxf(f0.y + g0.y, 0.f) * w0.y
            + fmaxf(f1.x + g1.x, 0.f) * w0.z + fmaxf(f1.y + g1.y, 0.f) * w0.w
            + fmaxf(f2.x + g2.x, 0.f) * w1.x + fmaxf(f2.y + g2.y, 0.f) * w1.y
            + fmaxf(f3.x + g3.x, 0.f) * w1.z + fmaxf(f3.y + g3.y, 0.f) * w1.w;
    r += __shfl_down_sync(0xffffffffu, r, 4);
    r += __shfl_down_sync(0xffffffffu, r, 2);
    r += __shfl_down_sync(0xffffffffu, r, 1);
    if (l == 0) out[e] = r + bias;
}

// ---- PDL launch helper ----
template <typename F, typename... Args>
static void launch_pdl(F f, int grid, int block, cudaStream_t st, Args... args) {
    cudaLaunchConfig_t cfg = {};
    cfg.gridDim = dim3(grid);
    cfg.blockDim = dim3(block);
    cfg.stream = st;
    cudaLaunchAttribute at[1];
    at[0].id = cudaLaunchAttributeProgrammaticStreamSerialization;
    at[0].val.programmaticStreamSerializationAllowed = 1;
    cfg.attrs = at;
    cfg.numAttrs = 1;
    cudaLaunchKernelEx(&cfg, f, args...);
}

extern "C" void kernel_launch(void* const* d_in, const int* in_sizes, int n_in,
                              void* d_out, int out_size) {
    const float* feats    = (const float*)d_in[0];
    const float* W1       = (const float*)d_in[1];
    const float* b1       = (const float*)d_in[2];
    const float* W2       = (const float*)d_in[3];
    const float* b2       = (const float*)d_in[4];
    const float* W3       = (const float*)d_in[5];
    const float* b3       = (const float*)d_in[6];
    const float* W4       = (const float*)d_in[7];
    const float* b4       = (const float*)d_in[8];
    const int*   src_seq  = (const int*)d_in[9];
    const int*   dst_seq  = (const int*)d_in[10];
    const int*   src_next = (const int*)d_in[11];
    const int*   dst_next = (const int*)d_in[12];
    float* out = (float*)d_out;

    // use_temporal=False in the reference: only snapshot t = T-1 = 2 contributes.
    const float* x_last = feats   + (size_t)2 * N_NODES * IN_DIM;
    const int*   src    = src_seq + (size_t)2 * N_EDGES;
    const int*   dst    = dst_seq + (size_t)2 * N_EDGES;

    // One-time host resources (no device memory) for fork/join overlap.
    static cudaStream_t s_side = nullptr;
    static cudaEvent_t  s_fork = nullptr, s_join = nullptr;
    if (!s_side) {
        cudaStreamCreateWithFlags(&s_side, cudaStreamNonBlocking);
        cudaEventCreateWithFlags(&s_fork, cudaEventDisableTiming);
        cudaEventCreateWithFlags(&s_join, cudaEventDisableTiming);
    }

    // Fork EARLY: prep + gemm1 (independent of graph) span the whole CSR build.
    cudaEventRecord(s_fork, 0);
    cudaStreamWaitEvent(s_side, s_fork, 0);
    {
        const int prep_n = IN_DIM * HID + HID * HID + HID * 128;   // 20480
        k_prep<<<(prep_n + 255) / 256, 256, 0, s_side>>>(W1, W2, W3);
    }
    k_gemm1_tc<<<NBLK_TC, 256, 0, s_side>>>(x_last);
    cudaEventRecord(s_join, s_side);

    k_deg<<<(N_EDGES / 4 + 255) / 256, 256>>>(src, dst);
    k_scan_local<<<NSCAN_BLOCKS, 256>>>();
    k_scan_add<<<(N_NODES + 255) / 256, 256>>>();
    k_csr_fill<<<(N_EDGES / 4 + 255) / 256, 256>>>(src, dst);

    cudaStreamWaitEvent(0, s_join, 0);

    k_gather<<<(N_NODES * 32 + 255) / 256, 256>>>(b1, 0);
    launch_pdl(k_gemm2_tc, NBLK_TC, 256, (cudaStream_t)0);
    k_gather<<<(N_NODES * 32 + 255) / 256, 256>>>(b2, 1);
    launch_pdl(k_post_tc, NBLK_TC, 256, (cudaStream_t)0, b3);
    launch_pdl(k_score, (int)(((long long)N_EDGES * 8 + 255) / 256), 256, (cudaStream_t)0,
               src_next, dst_next, W4, b4, out);
}